// round 13
// baseline (speedup 1.0000x reference)
#include <cuda_runtime.h>
#include <cuda_bf16.h>
#include <math.h>

// EMA with SD, chunked parallel scan (round 13).
// x (T=8192, D=128); h_a0, h_sd0, alpha (N=32, D=128).
// out: (T, 2N, D) fp32, then hN_a (N,D), hN_sd (N,D).
//
// pass1: CS=128 chunks of LS=64. Block (c,n) = 2 warps; warp w runs
//   sub-stream w (32 steps) with float4 lanes (LDG.128, full 512B row per
//   warp -> 2x bytes-in-flight vs r9 at same register count). Warp 0
//   publishes partials via smem; warp 1 merges exactly:
//     P' = W*P0 + P1,  A' = W*(A0 + (1-W)P0^2 - 2*P0*P1) + A1,  W = b^32
// pass2 (byte-identical to r12's 45us in-graph winner): CR=64 x LR=128,
//   float2 lanes, per-block prefix fold of summaries 0..2c-1 (W=b^64),
//   exact replay with __stcs streaming stores, sqrt.approx; c=CR-1 blocks
//   emit hN_a / hN_sd.

#define TT 8192
#define DD 128
#define NN 32
#define CS 128
#define LS 64
#define HS 32           // sub-stream length
#define CR 64
#define LR 128
#define LANES (NN * DD)

__device__ float g_P[CS * LANES];
__device__ float g_A[CS * LANES];

__device__ __forceinline__ float sqrt_fast(float v) {
    float r;
    asm("sqrt.approx.f32 %0, %1;" : "=f"(r) : "f"(v));
    return r;
}

// ---------------------------------------------------------------- pass 1
__global__ __launch_bounds__(64) void ema_pass1(
    const float* __restrict__ x,
    const float* __restrict__ alpha)
{
    const int c = blockIdx.x;            // 0..CS-1
    const int n = blockIdx.y;            // 0..NN-1
    const int w = threadIdx.x >> 5;      // sub-stream (0: steps 0..31, 1: 32..63)
    const int l = threadIdx.x & 31;
    const int d = 4 * l;
    const int idx = n * DD + d;

    const float4 al = *reinterpret_cast<const float4*>(alpha + idx);
    const float a0 = al.x, a1 = al.y, a2 = al.z, a3 = al.w;
    const float b0 = 1.0f - a0, b1 = 1.0f - a1, b2 = 1.0f - a2, b3 = 1.0f - a3;

    const float4* xp = reinterpret_cast<const float4*>(
        x + (size_t)(c * LS + w * HS) * DD + d);

    float g0 = 0.f, g1 = 0.f, g2 = 0.f, g3 = 0.f;
    float A0 = 0.f, A1 = 0.f, A2 = 0.f, A3 = 0.f;

#pragma unroll 8
    for (int i = 0; i < HS; ++i) {
        const float4 xv = xp[(size_t)i * (DD / 4)];
        float u;
        u = xv.x - g0; g0 = fmaf(a0, u, g0); A0 = b0 * fmaf(a0, u * u, A0);
        u = xv.y - g1; g1 = fmaf(a1, u, g1); A1 = b1 * fmaf(a1, u * u, A1);
        u = xv.z - g2; g2 = fmaf(a2, u, g2); A2 = b2 * fmaf(a2, u * u, A2);
        u = xv.w - g3; g3 = fmaf(a3, u, g3); A3 = b3 * fmaf(a3, u * u, A3);
    }

    __shared__ float4 sP[32];
    __shared__ float4 sA[32];
    if (w == 0) {
        sP[l] = make_float4(g0, g1, g2, g3);
        sA[l] = make_float4(A0, A1, A2, A3);
    }
    __syncthreads();

    if (w == 1) {
        // W = b^32 per lane (5 squarings)
        float W0, W1, W2, W3;
        { float p = b0 * b0; p *= p; p *= p; p *= p; W0 = p * p; }
        { float p = b1 * b1; p *= p; p *= p; p *= p; W1 = p * p; }
        { float p = b2 * b2; p *= p; p *= p; p *= p; W2 = p * p; }
        { float p = b3 * b3; p *= p; p *= p; p *= p; W3 = p * p; }

        const float4 P0 = sP[l];
        const float4 A0s = sA[l];
        // P' = W*P0 + P1 ; A' = W*(A0 + (1-W)P0^2 - 2*P0*P1) + A1
        const float Pm0 = fmaf(W0, P0.x, g0);
        const float Pm1 = fmaf(W1, P0.y, g1);
        const float Pm2 = fmaf(W2, P0.z, g2);
        const float Pm3 = fmaf(W3, P0.w, g3);
        const float Am0 = fmaf(W0, A0s.x + fmaf((1.f - W0) * P0.x, P0.x, -2.f * P0.x * g0), A0);
        const float Am1 = fmaf(W1, A0s.y + fmaf((1.f - W1) * P0.y, P0.y, -2.f * P0.y * g1), A1);
        const float Am2 = fmaf(W2, A0s.z + fmaf((1.f - W2) * P0.z, P0.z, -2.f * P0.z * g2), A2);
        const float Am3 = fmaf(W3, A0s.w + fmaf((1.f - W3) * P0.w, P0.w, -2.f * P0.w * g3), A3);

        const int s = c * LANES + idx;
        *reinterpret_cast<float4*>(g_P + s) = make_float4(Pm0, Pm1, Pm2, Pm3);
        *reinterpret_cast<float4*>(g_A + s) = make_float4(Am0, Am1, Am2, Am3);
    }
}

// ---------------------------------------------------------------- pass 2
// (byte-identical to round-12's winner)
__global__ __launch_bounds__(64) void ema_pass2(
    const float* __restrict__ x,
    const float* __restrict__ h_a0,
    const float* __restrict__ h_sd0,
    const float* __restrict__ alpha,
    float* __restrict__ out,
    int write_tail)
{
    const int c  = blockIdx.x;           // 0..CR-1
    const int n  = blockIdx.y;           // 0..NN-1
    const int d2 = threadIdx.x;          // 0..63
    const int idx = n * DD + 2 * d2;

    const float2 al = *reinterpret_cast<const float2*>(alpha + idx);
    const float a0 = al.x, a1 = al.y;
    const float b0 = 1.0f - a0, b1 = 1.0f - a1;

    // per-lane fold constants: W = b^64
    float W0, W1;
    {
        float p = b0 * b0; p *= p; p *= p; p *= p; p *= p; W0 = p * p;
    }
    {
        float p = b1 * b1; p *= p; p *= p; p *= p; p *= p; W1 = p * p;
    }
    const float Cq0 = W0 * (1.0f - W0), Cq1 = W1 * (1.0f - W1);
    const float m2W0 = -2.0f * W0,      m2W1 = -2.0f * W1;

    // entry state: fold summaries 0 .. 2c-1 (LS=64 granularity)
    const float2 hav = *reinterpret_cast<const float2*>(h_a0 + idx);
    const float2 sdv = *reinterpret_cast<const float2*>(h_sd0 + idx);
    float ha0 = hav.x, ha1 = hav.y;
    float hv0 = sdv.x * sdv.x, hv1 = sdv.y * sdv.y;

    const int nfold = 2 * c;
#pragma unroll 4
    for (int cc = 0; cc < nfold; ++cc) {
        const int s = cc * LANES + idx;
        const float2 P  = *reinterpret_cast<const float2*>(g_P + s);
        const float2 Aa = *reinterpret_cast<const float2*>(g_A + s);
        float hvn;
        hvn = fmaf(W0, hv0, fmaf(Cq0, ha0 * ha0, fmaf(m2W0 * P.x, ha0, Aa.x)));
        hv0 = fmaxf(hvn, 0.f);
        ha0 = fmaf(W0, ha0, P.x);
        hvn = fmaf(W1, hv1, fmaf(Cq1, ha1 * ha1, fmaf(m2W1 * P.y, ha1, Aa.y)));
        hv1 = fmaxf(hvn, 0.f);
        ha1 = fmaf(W1, ha1, P.y);
    }

    // exact replay with streaming stores
    const float2* xp = reinterpret_cast<const float2*>(x + (size_t)c * LR * DD + 2 * d2);
    float2* obase = reinterpret_cast<float2*>(out + (size_t)c * LR * 2 * NN * DD + n * DD + 2 * d2);

#pragma unroll 8
    for (int i = 0; i < LR; ++i) {
        const float2 xv = xp[(size_t)i * (DD / 2)];
        const float u0 = xv.x - ha0;
        const float u1 = xv.y - ha1;
        ha0 = fmaf(a0, u0, ha0);
        ha1 = fmaf(a1, u1, ha1);
        hv0 = b0 * fmaf(a0, u0 * u0, hv0);
        hv1 = b1 * fmaf(a1, u1 * u1, hv1);
        float2* op = obase + (size_t)i * (NN * DD);      // i * 4096 float2
        __stcs(op, make_float2(ha0, ha1));
        __stcs(op + (NN * DD / 2), make_float2(sqrt_fast(hv0), sqrt_fast(hv1)));
    }

    // tail: final states from the last chunk's replay-exit state
    if (write_tail && c == CR - 1) {
        const size_t base = (size_t)TT * 2 * NN * DD;
        *reinterpret_cast<float2*>(out + base + idx) = make_float2(ha0, ha1);
        *reinterpret_cast<float2*>(out + base + LANES + idx) =
            make_float2(sqrt_fast(hv0), sqrt_fast(hv1));
    }
}

extern "C" void kernel_launch(void* const* d_in, const int* in_sizes, int n_in,
                              void* d_out, int out_size)
{
    const float* x     = (const float*)d_in[0];
    const float* h_a0  = (const float*)d_in[1];
    const float* h_sd0 = (const float*)d_in[2];
    const float* alpha = (const float*)d_in[3];
    float* out = (float*)d_out;

    const int main_elems = TT * 2 * NN * DD;
    const int write_tail = (out_size > main_elems) ? 1 : 0;

    dim3 grid1(CS, NN);
    ema_pass1<<<grid1, 64>>>(x, alpha);
    dim3 grid2(CR, NN);
    ema_pass2<<<grid2, 64>>>(x, h_a0, h_sd0, alpha, out, write_tail);
}